// round 16
// baseline (speedup 1.0000x reference)
#include <cuda_runtime.h>
#include <cuda_bf16.h>
#include <cuda_pipeline.h>
#include <cub/cub.cuh>
#include <math.h>
#include <stdint.h>

#define NENT 512
#define DIM  768
#define HID  256
#define NT   16
#define NN   (NENT * NENT)
#define TI 8
#define TJ 16
#define PAD 65536           // >= max same-batch pairs (65024)

// ---------------- static device scratch (no allocs allowed) ----------------
__device__ float g_G[NENT * 6 * HID];   // [i][ s_i+b | c_i+b | d_i+b | s_j | c_j | d_j ]
__device__ float g_GTc[HID * NENT];     // transposed c_j block: [dim][entity]
__device__ float g_stats[NENT * 4];     // per entity: S1c, Q1c, S2c, Q2c
__device__ float g_dotc[NENT * NENT];   // hi_c . hj_c
__device__ unsigned long long g_ckeys[PAD];
__device__ unsigned long long g_ckeys_s[PAD];
__device__ int g_ncand;
__device__ int g_ncand_b[4];
__device__ unsigned char g_sort_tmp[16u << 20];

// f32x2 helpers — each packed lane is an exact IEEE-RN scalar op.
#define ADD2(out, a, b) asm("add.rn.f32x2 %0, %1, %2;" : "=l"(out) : "l"(a), "l"(b))
#define MUL2(out, a, b) asm("mul.rn.f32x2 %0, %1, %2;" : "=l"(out) : "l"(a), "l"(b))
#define FMA2(acc, a, b) asm("fma.rn.f32x2 %0, %1, %2, %0;" : "+l"(acc) : "l"(a), "l"(b))
#define FMA2O(out, a, b, c) asm("fma.rn.f32x2 %0, %1, %2, %3;" : "=l"(out) : "l"(a), "l"(b), "l"(c))
#define PACK2(out, v) asm("mov.b64 %0, {%1, %1};" : "=l"(out) : "r"(__float_as_uint(v)))
#define SPLIT2(lo, hi, in) do { unsigned _l, _h; \
    asm("mov.b64 {%0, %1}, %2;" : "=r"(_l), "=r"(_h) : "l"(in)); \
    lo = __uint_as_float(_l); hi = __uint_as_float(_h); } while (0)

// ---------------------------------------------------------------------------
// clear: candidate keys + counters + selected plane (coalesced; removes the
// per-pair scattered selout store from paira).
// ---------------------------------------------------------------------------
__global__ void clear_kernel(float* __restrict__ selout) {
    int tid = blockIdx.x * blockDim.x + threadIdx.x;
    int stride = gridDim.x * blockDim.x;
    for (int k = tid; k < PAD; k += stride) g_ckeys[k] = 0ull;
    float4 z4 = make_float4(0.f, 0.f, 0.f, 0.f);
    for (int k = tid; k < NN / 4; k += stride) ((float4*)selout)[k] = z4;
    if (tid == 0) { g_ncand = 0; g_ncand_b[0] = 0; g_ncand_b[1] = 0; g_ncand_b[2] = 0; g_ncand_b[3] = 0; }
}

// ---------------------------------------------------------------------------
// Kernel 1: six fused projections — M-tile 32 (384 blocks: fixes the 192-on-148
// wave imbalance). Per-output k-accumulation order unchanged => bit-identical.
// ---------------------------------------------------------------------------
__global__ void __launch_bounds__(256) gemm6_kernel(
    const float* __restrict__ E,
    const float* __restrict__ sW1, const float* __restrict__ cW1, const float* __restrict__ dW1,
    const float* __restrict__ sb1, const float* __restrict__ cb1, const float* __restrict__ db1)
{
    __shared__ __align__(16) float As[2][32][20];
    __shared__ float4 Bs[2][16 * 16];

    int z = blockIdx.z;
    const float* W = (z % 3 == 0) ? sW1 : (z % 3 == 1) ? cW1 : dW1;
    const float* bias = nullptr;
    if (z == 0) bias = sb1; else if (z == 1) bias = cb1; else if (z == 2) bias = db1;
    int rowoff  = (z < 3) ? 0 : DIM;
    int colbase = z * HID;

    int m0 = blockIdx.y * 32;
    int n0 = blockIdx.x * 64;
    int tid = threadIdx.x;
    int tx = tid & 15, ty = tid >> 4;      // ty in [0,16): rows ty*2, ty*2+1
    int arow = tid >> 2, aq = tid & 3;     // A staging (tid < 128): 32 rows x 4 quads
    int brow = tid >> 4, bn = tid & 15;    // B staging: 16 k x 16 float4

    if (tid < 128)
        __pipeline_memcpy_async(&As[0][arow][aq * 4],
                                E + (size_t)(m0 + arow) * DIM + 0 + aq * 4, 16);
    __pipeline_memcpy_async(&Bs[0][brow * 16 + bn],
                            W + (size_t)(rowoff + 0 + brow) * HID + n0 + bn * 4, 16);
    __pipeline_commit();

    unsigned long long accp[2][2] = {};

    const int NC = DIM / 16;
    for (int c = 0; c < NC; c++) {
        if (c < NC - 1) {
            int bb = (c + 1) & 1;
            int k0 = (c + 1) * 16;
            if (tid < 128)
                __pipeline_memcpy_async(&As[bb][arow][aq * 4],
                                        E + (size_t)(m0 + arow) * DIM + k0 + aq * 4, 16);
            __pipeline_memcpy_async(&Bs[bb][brow * 16 + bn],
                                    W + (size_t)(rowoff + k0 + brow) * HID + n0 + bn * 4, 16);
            __pipeline_commit();
            __pipeline_wait_prior(1);
        } else {
            __pipeline_wait_prior(0);
        }
        __syncthreads();

        const float (*A)[20] = As[c & 1];
        const ulonglong2* B2 = (const ulonglong2*)Bs[c & 1];
        #pragma unroll
        for (int k = 0; k < 16; k++) {
            unsigned long long a0p, a1p;
            PACK2(a0p, A[ty * 2 + 0][k]);
            PACK2(a1p, A[ty * 2 + 1][k]);
            ulonglong2 b = B2[k * 16 + tx];
            FMA2(accp[0][0], a0p, b.x); FMA2(accp[0][1], a0p, b.y);
            FMA2(accp[1][0], a1p, b.x); FMA2(accp[1][1], a1p, b.y);
        }
        __syncthreads();
    }

    #pragma unroll
    for (int u = 0; u < 2; u++) {
        int gr = m0 + ty * 2 + u;
        int gc = n0 + tx * 4;
        float4 o;
        SPLIT2(o.x, o.y, accp[u][0]);
        SPLIT2(o.z, o.w, accp[u][1]);
        if (bias) { o.x += bias[gc]; o.y += bias[gc + 1]; o.z += bias[gc + 2]; o.w += bias[gc + 3]; }
        *(float4*)(g_G + (size_t)gr * (6 * HID) + colbase + gc) = o;
    }
}

// ---------------------------------------------------------------------------
__device__ __forceinline__ float warpsum(float v) {
    v += __shfl_xor_sync(0xffffffffu, v, 16);
    v += __shfl_xor_sync(0xffffffffu, v, 8);
    v += __shfl_xor_sync(0xffffffffu, v, 4);
    v += __shfl_xor_sync(0xffffffffu, v, 2);
    v += __shfl_xor_sync(0xffffffffu, v, 1);
    return v;
}

// libdevice erff: FMA-polynomial, no MUFU — keep everywhere (R5 lesson).
__device__ __forceinline__ float gelu_exact(float x) {
    return 0.5f * x * (1.0f + erff(x * 0.70710678118654752440f));
}

// ---------------------------------------------------------------------------
// prep: transpose c_j into g_GTc + per-entity (sum, sumsq) stats.
// ---------------------------------------------------------------------------
__global__ void __launch_bounds__(256) prep_kernel() {
    int b = blockIdx.x;
    int tid = threadIdx.x;
    if (b < 128) {
        __shared__ float t[32][33];
        int e0 = (b & 15) * 32;
        int d0 = (b >> 4) * 32;
        int tx = tid & 31, ty = tid >> 5;
        #pragma unroll
        for (int r = 0; r < 4; r++) {
            int row = ty + r * 8;
            t[row][tx] = g_G[(size_t)(e0 + row) * 1536 + 1024 + d0 + tx];
        }
        __syncthreads();
        #pragma unroll
        for (int r = 0; r < 4; r++) {
            int row = ty + r * 8;
            g_GTc[(size_t)(d0 + row) * NENT + e0 + tx] = t[tx][row];
        }
    } else {
        int warp = tid >> 5, lane = tid & 31;
        int e = (b - 128) * 8 + warp;
        const float* gr = g_G + (size_t)e * 1536;
        float s1 = 0.f, q1 = 0.f, s2 = 0.f, q2 = 0.f;
        #pragma unroll
        for (int q = 0; q < 8; q++) {
            float a = gr[256 + lane * 8 + q];
            float c = gr[1024 + lane * 8 + q];
            s1 += a; q1 = fmaf(a, a, q1);
            s2 += c; q2 = fmaf(c, c, q2);
        }
        s1 = warpsum(s1); q1 = warpsum(q1); s2 = warpsum(s2); q2 = warpsum(q2);
        if (lane == 0) {
            float4 o; o.x = s1; o.y = q1; o.z = s2; o.w = q2;
            *(float4*)(g_stats + e * 4) = o;
        }
    }
}

// ---------------------------------------------------------------------------
// dotc[i][j] = hi_c[i] . hj_c[j]
// ---------------------------------------------------------------------------
__global__ void __launch_bounds__(256) dotc_kernel() {
    __shared__ float As[64][17];
    __shared__ float Bs2[64][17];

    int m0 = blockIdx.y * 64;
    int n0 = blockIdx.x * 64;
    int tid = threadIdx.x;
    int tx = tid & 15, ty = tid >> 4;
    int lrow = tid >> 2, lkq = tid & 3;

    float acc[4][4] = {};

    for (int k0 = 0; k0 < HID; k0 += 16) {
        __syncthreads();
        {
            float4 a = *(const float4*)(g_G + (size_t)(m0 + lrow) * 1536 + 256 + k0 + lkq * 4);
            As[lrow][lkq * 4 + 0] = a.x; As[lrow][lkq * 4 + 1] = a.y;
            As[lrow][lkq * 4 + 2] = a.z; As[lrow][lkq * 4 + 3] = a.w;
            float4 c = *(const float4*)(g_G + (size_t)(n0 + lrow) * 1536 + 1024 + k0 + lkq * 4);
            Bs2[lrow][lkq * 4 + 0] = c.x; Bs2[lrow][lkq * 4 + 1] = c.y;
            Bs2[lrow][lkq * 4 + 2] = c.z; Bs2[lrow][lkq * 4 + 3] = c.w;
        }
        __syncthreads();
        #pragma unroll
        for (int k = 0; k < 16; k++) {
            float a0 = As[ty * 4 + 0][k], a1 = As[ty * 4 + 1][k];
            float a2 = As[ty * 4 + 2][k], a3 = As[ty * 4 + 3][k];
            float b0 = Bs2[tx * 4 + 0][k], b1 = Bs2[tx * 4 + 1][k];
            float b2 = Bs2[tx * 4 + 2][k], b3 = Bs2[tx * 4 + 3][k];
            acc[0][0] = fmaf(a0, b0, acc[0][0]); acc[0][1] = fmaf(a0, b1, acc[0][1]);
            acc[0][2] = fmaf(a0, b2, acc[0][2]); acc[0][3] = fmaf(a0, b3, acc[0][3]);
            acc[1][0] = fmaf(a1, b0, acc[1][0]); acc[1][1] = fmaf(a1, b1, acc[1][1]);
            acc[1][2] = fmaf(a1, b2, acc[1][2]); acc[1][3] = fmaf(a1, b3, acc[1][3]);
            acc[2][0] = fmaf(a2, b0, acc[2][0]); acc[2][1] = fmaf(a2, b1, acc[2][1]);
            acc[2][2] = fmaf(a2, b2, acc[2][2]); acc[2][3] = fmaf(a2, b3, acc[2][3]);
            acc[3][0] = fmaf(a3, b0, acc[3][0]); acc[3][1] = fmaf(a3, b1, acc[3][1]);
            acc[3][2] = fmaf(a3, b2, acc[3][2]); acc[3][3] = fmaf(a3, b3, acc[3][3]);
        }
    }
    #pragma unroll
    for (int u = 0; u < 4; u++) {
        float4 o; o.x = acc[u][0]; o.y = acc[u][1]; o.z = acc[u][2]; o.w = acc[u][3];
        *(float4*)(g_dotc + (size_t)(m0 + ty * 4 + u) * NENT + n0 + tx * 4) = o;
    }
}

// ---------------------------------------------------------------------------
// pair_c: cp.async double-buffered staging + FFMA2 weight-multiply (R14/R15).
// ---------------------------------------------------------------------------
#define PAIRC_SMEM ((2 * 16 * 256 + 256 * 16 + 2 * 256 + 256 + 16) * 4)

__global__ void __launch_bounds__(256) pairc_kernel(
    const float* __restrict__ cW2, const float* __restrict__ cb2,
    const float* __restrict__ c_g, const float* __restrict__ c_b,
    float* __restrict__ out)
{
    extern __shared__ float shc[];
    float*  sh_x    = shc;                             // [2][16][256]
    float*  sh_c2   = shc + 8192;                      // [256][16]
    float2* sh_gb   = (float2*)(shc + 8192 + 4096);    // [256]
    float*  sh_hic  = shc + 8192 + 4096 + 512;         // [256]
    float*  sh_cb2v = sh_hic + 256;                    // [16]

    int tid = threadIdx.x;
    int i = blockIdx.y;
    int j0 = blockIdx.x * 256;
    int j = j0 + tid;

    #pragma unroll
    for (int q = 0; q < 4; q++) {
        int f = q * 256 + tid;
        int dl = f >> 6, c4 = f & 63;
        __pipeline_memcpy_async(sh_x + dl * 256 + c4 * 4,
                                g_GTc + (size_t)dl * NENT + j0 + c4 * 4, 16);
    }
    __pipeline_commit();

    sh_hic[tid] = g_G[(size_t)i * 1536 + 256 + tid];
    sh_gb[tid] = make_float2(c_g[tid], c_b[tid]);
    for (int k = tid; k < 1024; k += 256)
        ((float4*)sh_c2)[k] = ((const float4*)cW2)[k];
    if (tid < 16) sh_cb2v[tid] = cb2[tid];

    const float inv256 = 1.0f / 256.0f;
    float4 stj = *(const float4*)(g_stats + j * 4);
    float S1 = g_stats[i * 4 + 0];
    float Q1 = g_stats[i * 4 + 1];
    float dot = g_dotc[(size_t)i * NENT + j];
    float m = (S1 + stj.z) * inv256;
    float var = fmaf(-m, m, (Q1 + 2.0f * dot + stj.w) * inv256);
    float rs = rsqrtf(var + 1e-5f);

    unsigned long long vp[8];
    #pragma unroll
    for (int t = 0; t < 8; t++) vp[t] = 0ull;

    __syncthreads();

    for (int c = 0; c < 16; c++) {
        if (c < 15) {
            int bb = (c + 1) & 1;
            #pragma unroll
            for (int q = 0; q < 4; q++) {
                int f = q * 256 + tid;
                int dl = f >> 6, c4 = f & 63;
                int d = (c + 1) * 16 + dl;
                __pipeline_memcpy_async(sh_x + bb * 4096 + dl * 256 + c4 * 4,
                                        g_GTc + (size_t)d * NENT + j0 + c4 * 4, 16);
            }
            __pipeline_commit();
            __pipeline_wait_prior(1);
        } else {
            __pipeline_wait_prior(0);
        }
        __syncthreads();

        const float* xb = sh_x + (c & 1) * 4096;
        #pragma unroll
        for (int dl = 0; dl < 16; dl++) {
            int d = c * 16 + dl;
            float x = xb[dl * 256 + tid] + sh_hic[d];
            float2 gb = sh_gb[d];
            float hn = fmaf((x - m) * rs, gb.x, gb.y);
            float ge = gelu_exact(hn);
            unsigned long long gep;
            PACK2(gep, ge);
            const ulonglong2* w2 = (const ulonglong2*)(sh_c2 + d * 16);
            ulonglong2 q0 = w2[0], q1 = w2[1], q2 = w2[2], q3 = w2[3];
            FMA2(vp[0], gep, q0.x); FMA2(vp[1], gep, q0.y);
            FMA2(vp[2], gep, q1.x); FMA2(vp[3], gep, q1.y);
            FMA2(vp[4], gep, q2.x); FMA2(vp[5], gep, q2.y);
            FMA2(vp[6], gep, q3.x); FMA2(vp[7], gep, q3.y);
        }
        __syncthreads();
    }

    float* orow = out + ((size_t)i * NENT + j) * 18 + 1;
    #pragma unroll
    for (int t = 0; t < 8; t++) {
        float lo, hi;
        SPLIT2(lo, hi, vp[t]);
        orow[2 * t + 0] = lo + sh_cb2v[2 * t + 0];
        orow[2 * t + 1] = hi + sh_cb2v[2 * t + 1];
    }
}

// ---------------------------------------------------------------------------
// pair_a: s + d heads, f32x2-packed (R15, bit-identical). selout zeroing
// moved to clear_kernel — one fewer scattered store per pair.
// ---------------------------------------------------------------------------
__global__ void __launch_bounds__(256, 4) paira_kernel(
    const float* __restrict__ sW2, const float* __restrict__ sb2,
    const float* __restrict__ s_g, const float* __restrict__ s_b,
    const float* __restrict__ dW2, const float* __restrict__ db2,
    const int* __restrict__ ebatch,
    float* __restrict__ out)
{
    extern __shared__ float sh[];
    float* sh_hj  = sh;                       // [2][TJ][256]  (s_j, d_j)
    float* sh_sg  = sh + 2 * TJ * 256;        // 256
    float* sh_sb  = sh_sg + 256;
    int*   sh_jb  = (int*)(sh_sb + 256);      // 16

    int i0 = blockIdx.y * TI, j0 = blockIdx.x * TJ;
    int tid = threadIdx.x, warp = tid >> 5, lane = tid & 31;

    for (int v = tid; v < 2 * TJ * 64; v += 256) {
        int h = v / (TJ * 64); int rem = v % (TJ * 64);
        int jj = rem / 64; int c4 = rem % 64;
        float4 val = *(const float4*)(g_G + (size_t)(j0 + jj) * 1536 + (3 + 2 * h) * 256 + c4 * 4);
        *(float4*)(sh_hj + ((h * TJ + jj) * 256) + c4 * 4) = val;
    }
    { int c = tid; sh_sg[c] = s_g[c]; sh_sb[c] = s_b[c]; }
    if (tid < 16) sh_jb[tid] = ebatch[j0 + tid];
    __syncthreads();

    int i = i0 + warp;
    int d0 = lane * 8;

    unsigned long long hisp[4], hidp[4];
    {
        const unsigned long long* gr64 = (const unsigned long long*)(g_G + (size_t)i * 1536);
        int h0 = lane * 4;
        #pragma unroll
        for (int h = 0; h < 4; h++) {
            hisp[h] = gr64[h0 + h];          // floats [d0, d0+8)
            hidp[h] = gr64[256 + h0 + h];    // floats [512+d0, 512+d0+8)
        }
    }
    float s2[8], d2v[8];
    #pragma unroll
    for (int q = 0; q < 8; q++) { s2[q] = sW2[d0 + q]; d2v[q] = dW2[d0 + q]; }

    float sbias2 = sb2[0], dbias2 = db2[0];
    int bi = ebatch[i];
    const float inv256 = 1.0f / 256.0f;
    const unsigned long long* sg64 = (const unsigned long long*)(sh_sg + d0);
    const unsigned long long* sb64 = (const unsigned long long*)(sh_sb + d0);

    for (int jj = 0; jj < TJ; jj++) {
        int j = j0 + jj;

        // -------- s head (bit-identical op sequence) --------
        const unsigned long long* hj64 =
            (const unsigned long long*)(sh_hj + (0 * TJ + jj) * 256 + d0);
        unsigned long long xp[4];
        float x[8];
        #pragma unroll
        for (int h = 0; h < 4; h++) {
            unsigned long long hjp = hj64[h];
            ADD2(xp[h], hisp[h], hjp);
            SPLIT2(x[2 * h], x[2 * h + 1], xp[h]);
        }
        float ps = 0.f;
        #pragma unroll
        for (int q = 0; q < 8; q++) ps += x[q];
        float m = warpsum(ps) * inv256;
        float nm = -m;
        unsigned long long nm2;
        PACK2(nm2, nm);
        unsigned long long ddp[4];
        float dd[8];
        #pragma unroll
        for (int h = 0; h < 4; h++) {
            ADD2(ddp[h], xp[h], nm2);
            SPLIT2(dd[2 * h], dd[2 * h + 1], ddp[h]);
        }
        float pv = 0.f;
        #pragma unroll
        for (int q = 0; q < 8; q++) pv = fmaf(dd[q], dd[q], pv);
        float rs = rsqrtf(warpsum(pv) * inv256 + 1e-5f);
        unsigned long long rs2;
        PACK2(rs2, rs);
        float acc = 0.f;
        #pragma unroll
        for (int h = 0; h < 4; h++) {
            unsigned long long t, hnp;
            MUL2(t, ddp[h], rs2);
            FMA2O(hnp, t, sg64[h], sb64[h]);
            float hn0, hn1;
            SPLIT2(hn0, hn1, hnp);
            acc = fmaf(gelu_exact(hn0), s2[2 * h + 0], acc);
            acc = fmaf(gelu_exact(hn1), s2[2 * h + 1], acc);
        }
        acc = warpsum(acc);
        float score = 1.0f / (1.0f + expf(-(acc + sbias2)));

        // -------- d head --------
        const unsigned long long* hjd64 =
            (const unsigned long long*)(sh_hj + (1 * TJ + jj) * 256 + d0);
        float acc2 = 0.f;
        #pragma unroll
        for (int h = 0; h < 4; h++) {
            unsigned long long xxp;
            ADD2(xxp, hidp[h], hjd64[h]);
            float xx0, xx1;
            SPLIT2(xx0, xx1, xxp);
            acc2 = fmaf(gelu_exact(xx0), d2v[2 * h + 0], acc2);
            acc2 = fmaf(gelu_exact(xx1), d2v[2 * h + 1], acc2);
        }
        acc2 = warpsum(acc2);
        float dir = 1.0f / (1.0f + expf(-(acc2 + dbias2)));

        if (lane == 0) {
            size_t pidx = (size_t)i * NENT + j;
            float* orow = out + pidx * 18;
            orow[0]  = score;
            orow[17] = dir;
            int cand = (bi == sh_jb[jj]) && (i != j) && (score >= 0.5f);
            if (cand) {
                int pos = atomicAdd(&g_ncand, 1);
                atomicAdd(&g_ncand_b[bi], 1);
                if (pos < PAD) {
                    unsigned bits = __float_as_uint(score);
                    unsigned long long key =
                        ((unsigned long long)(unsigned)bi << 42) |
                        ((unsigned long long)(bits - 0x3F000000u) << 18) |
                        (unsigned long long)((~(unsigned)pidx) & 0x3FFFFu);
                    g_ckeys[pos] = key;
                }
            }
        }
    }
}

// ---------------------------------------------------------------------------
// Greedy quota filter — batch-parallel: 4 warps, one per batch segment.
// ---------------------------------------------------------------------------
__global__ void __launch_bounds__(128) greedy_kernel(
    const unsigned long long* __restrict__ keys_s, float* __restrict__ selout)
{
    __shared__ int counts[NENT];
    __shared__ unsigned em[NENT];

    int tid = threadIdx.x;
    for (int e = tid; e < NENT; e += 128) { counts[e] = 0; em[e] = 0u; }
    __syncthreads();

    int warp = tid >> 5, lane = tid & 31;
    unsigned lt = (1u << lane) - 1u;

    int c3 = g_ncand_b[3], c2 = g_ncand_b[2], c1 = g_ncand_b[1], c0 = g_ncand_b[0];
    int b = 3 - warp;
    int start, len;
    if      (b == 3) { start = 0;            len = c3; }
    else if (b == 2) { start = c3;           len = c2; }
    else if (b == 1) { start = c3 + c2;      len = c1; }
    else             { start = c3 + c2 + c1; len = c0; }
    int end = start + len;
    if (end > PAD) end = PAD;

    unsigned long long knext = (start + lane < end) ? __ldg(keys_s + start + lane) : 0ull;

    for (int base = start; base < end; base += 32) {
        unsigned long long k = knext;
        int nb = base + 32;
        knext = (nb + lane < end) ? __ldg(keys_s + nb + lane) : 0ull;

        int active = (base + lane) < end;
        unsigned pidx = (~(unsigned)k) & 0x3FFFFu;
        int s = pidx >> 9, t = pidx & (NENT - 1);
        int cs = counts[s], ct = counts[t];
        int pre = active && (cs < 5) && (ct < 5);
        unsigned pm = __ballot_sync(0xffffffffu, pre);
        if (!pm) continue;

        if (pre) { atomicOr(&em[s], 1u << lane); atomicOr(&em[t], 1u << lane); }
        __syncwarp();
        unsigned Ms = 0u, Mt = 0u;
        if (pre) { Ms = em[s]; Mt = em[t]; }
        int ub_s = __popc(Ms & lt);
        int ub_t = __popc(Mt & lt);
        int sure = pre && (cs + ub_s < 5) && (ct + ub_t < 5);
        unsigned smask = __ballot_sync(0xffffffffu, sure);
        unsigned u = pm & ~smask;
        int accepted = sure;
        if (u) {
            int ok = 0;
            int es = __popc(Ms & smask & lt);
            int et = __popc(Mt & smask & lt);
            unsigned uu = u;
            while (uu) {
                int l = __ffs(uu) - 1;
                int okl_local = ((cs + es) < 5) && ((ct + et) < 5);
                int okl = __shfl_sync(0xffffffffu, okl_local, l);
                int sl  = __shfl_sync(0xffffffffu, s, l);
                int tl  = __shfl_sync(0xffffffffu, t, l);
                if (okl) {
                    es += (sl == s) + (tl == s);
                    et += (sl == t) + (tl == t);
                    if (lane == l) ok = 1;
                }
                uu &= uu - 1;
            }
            accepted |= ok;
        }
        if (accepted) {
            atomicAdd(&counts[s], 1);
            atomicAdd(&counts[t], 1);
            selout[pidx] = 1.0f;
        }
        __syncwarp();
        if (pre) { em[s] = 0u; em[t] = 0u; }
        __syncwarp();
    }
}

// ---------------------------------------------------------------------------
extern "C" void kernel_launch(void* const* d_in, const int* in_sizes, int n_in,
                              void* d_out, int out_size) {
    const float* E      = (const float*)d_in[0];
    const int*   ebatch = (const int*)d_in[1];
    const float* sW1 = (const float*)d_in[3];
    const float* sb1 = (const float*)d_in[4];
    const float* s_g = (const float*)d_in[5];
    const float* s_b = (const float*)d_in[6];
    const float* sW2 = (const float*)d_in[7];
    const float* sb2 = (const float*)d_in[8];
    const float* cW1 = (const float*)d_in[9];
    const float* cb1 = (const float*)d_in[10];
    const float* c_g = (const float*)d_in[11];
    const float* c_b = (const float*)d_in[12];
    const float* cW2 = (const float*)d_in[13];
    const float* cb2 = (const float*)d_in[14];
    const float* dW1 = (const float*)d_in[15];
    const float* db1 = (const float*)d_in[16];
    const float* dW2 = (const float*)d_in[17];
    const float* db2 = (const float*)d_in[18];

    float* out = (float*)d_out;
    float* selout = out + ((size_t)out_size - NN);

    // Stream/events created ONCE on the first call (precedes the harness's
    // pre-capture memory baseline), reused thereafter — R12 leak fix.
    static cudaStream_t s2 = nullptr;
    static cudaEvent_t evF = nullptr, evJ = nullptr;
    if (s2 == nullptr) {
        cudaStreamCreate(&s2);
        cudaEventCreateWithFlags(&evF, cudaEventDisableTiming);
        cudaEventCreateWithFlags(&evJ, cudaEventDisableTiming);
        cudaFuncSetAttribute(pairc_kernel, cudaFuncAttributeMaxDynamicSharedMemorySize, PAIRC_SMEM);
        cudaFuncSetAttribute(paira_kernel, cudaFuncAttributeMaxDynamicSharedMemorySize,
                             (2 * TJ * 256 + 2 * 256) * 4 + 16 * 4);
    }
    int shbytes = (2 * TJ * 256 + 2 * 256) * 4 + 16 * 4;

    // R11 topology: unified gemm6 first, then fork the c-chain.
    clear_kernel<<<256, 256>>>(selout);
    gemm6_kernel<<<dim3(HID / 64, NENT / 32, 6), 256>>>(E, sW1, cW1, dW1, sb1, cb1, db1);

    cudaEventRecord(evF, 0);
    cudaStreamWaitEvent(s2, evF, 0);

    // stream 0: paira -> sort -> greedy
    paira_kernel<<<dim3(NENT / TJ, NENT / TI), 256, shbytes>>>(
        sW2, sb2, s_g, s_b, dW2, db2, ebatch, out);

    // stream s2: prep -> dotc -> pairc
    prep_kernel<<<192, 256, 0, s2>>>();
    dotc_kernel<<<dim3(NENT / 64, NENT / 64), 256, 0, s2>>>();
    pairc_kernel<<<dim3(NENT / 256, NENT), 256, PAIRC_SMEM, s2>>>(cW2, cb2, c_g, c_b, out);
    cudaEventRecord(evJ, s2);

    void *pck, *pcks, *ptmp;
    cudaGetSymbolAddress(&pck,  g_ckeys);
    cudaGetSymbolAddress(&pcks, g_ckeys_s);
    cudaGetSymbolAddress(&ptmp, g_sort_tmp);
    size_t tb = 0;
    cub::DeviceRadixSort::SortKeysDescending(nullptr, tb,
        (const unsigned long long*)pck, (unsigned long long*)pcks, PAD, 0, 44, 0);
    if (tb > (size_t)(16u << 20)) tb = (size_t)(16u << 20);
    cub::DeviceRadixSort::SortKeysDescending(ptmp, tb,
        (const unsigned long long*)pck, (unsigned long long*)pcks, PAD, 0, 44, 0);

    greedy_kernel<<<1, 128>>>((const unsigned long long*)pcks, selout);

    // join pairc chain back into stream 0 before capture ends
    cudaStreamWaitEvent(0, evJ, 0);
}

// round 17
// speedup vs baseline: 1.0588x; 1.0588x over previous
#include <cuda_runtime.h>
#include <cuda_bf16.h>
#include <cuda_pipeline.h>
#include <cub/cub.cuh>
#include <math.h>
#include <stdint.h>

#define NENT 512
#define DIM  768
#define HID  256
#define NT   16
#define NN   (NENT * NENT)
#define TI 8
#define TJ 16
#define PAD 65536           // >= max same-batch pairs (65024)

// ---------------- static device scratch (no allocs allowed) ----------------
__device__ float g_G[NENT * 6 * HID];   // [i][ s_i+b | c_i+b | d_i+b | s_j | c_j | d_j ]
__device__ float g_GTc[HID * NENT];     // transposed c_j block: [dim][entity]
__device__ float g_stats[NENT * 4];     // per entity: S1c, Q1c, S2c, Q2c
__device__ float g_dotc[NENT * NENT];   // hi_c . hj_c
__device__ unsigned long long g_ckeys[PAD];
__device__ unsigned long long g_ckeys_s[PAD];
__device__ int g_ncand;
__device__ int g_ncand_b[4];
__device__ unsigned char g_sort_tmp[16u << 20];

// f32x2 helpers — each packed lane is an exact IEEE-RN scalar op.
#define ADD2(out, a, b) asm("add.rn.f32x2 %0, %1, %2;" : "=l"(out) : "l"(a), "l"(b))
#define MUL2(out, a, b) asm("mul.rn.f32x2 %0, %1, %2;" : "=l"(out) : "l"(a), "l"(b))
#define FMA2(acc, a, b) asm("fma.rn.f32x2 %0, %1, %2, %0;" : "+l"(acc) : "l"(a), "l"(b))
#define FMA2O(out, a, b, c) asm("fma.rn.f32x2 %0, %1, %2, %3;" : "=l"(out) : "l"(a), "l"(b), "l"(c))
#define PACK2(out, v) asm("mov.b64 %0, {%1, %1};" : "=l"(out) : "r"(__float_as_uint(v)))
#define SPLIT2(lo, hi, in) do { unsigned _l, _h; \
    asm("mov.b64 {%0, %1}, %2;" : "=r"(_l), "=r"(_h) : "l"(in)); \
    lo = __uint_as_float(_l); hi = __uint_as_float(_h); } while (0)

// ---------------------------------------------------------------------------
// clear: candidate keys + counters + selected plane (coalesced; removes the
// per-pair scattered selout store from paira).
// ---------------------------------------------------------------------------
__global__ void clear_kernel(float* __restrict__ selout) {
    int tid = blockIdx.x * blockDim.x + threadIdx.x;
    int stride = gridDim.x * blockDim.x;
    for (int k = tid; k < PAD; k += stride) g_ckeys[k] = 0ull;
    float4 z4 = make_float4(0.f, 0.f, 0.f, 0.f);
    for (int k = tid; k < NN / 4; k += stride) ((float4*)selout)[k] = z4;
    if (tid == 0) { g_ncand = 0; g_ncand_b[0] = 0; g_ncand_b[1] = 0; g_ncand_b[2] = 0; g_ncand_b[3] = 0; }
}

// ---------------------------------------------------------------------------
// Kernel 1: six fused projections — R15 version (M-tile 64, cp.async buffered,
// packed accumulators). The R16 M-tile-32 variant regressed (2x B staging
// traffic + halved FMA ILP); reverted.
// ---------------------------------------------------------------------------
__global__ void __launch_bounds__(256) gemm6_kernel(
    const float* __restrict__ E,
    const float* __restrict__ sW1, const float* __restrict__ cW1, const float* __restrict__ dW1,
    const float* __restrict__ sb1, const float* __restrict__ cb1, const float* __restrict__ db1)
{
    __shared__ __align__(16) float As[2][64][20];
    __shared__ float4 Bs[2][16 * 16];

    int z = blockIdx.z;
    const float* W = (z % 3 == 0) ? sW1 : (z % 3 == 1) ? cW1 : dW1;
    const float* bias = nullptr;
    if (z == 0) bias = sb1; else if (z == 1) bias = cb1; else if (z == 2) bias = db1;
    int rowoff  = (z < 3) ? 0 : DIM;
    int colbase = z * HID;

    int m0 = blockIdx.y * 64;
    int n0 = blockIdx.x * 64;
    int tid = threadIdx.x;
    int tx = tid & 15, ty = tid >> 4;
    int arow = tid >> 2, aq = tid & 3;
    int brow = tid >> 4, bn = tid & 15;

    __pipeline_memcpy_async(&As[0][arow][aq * 4],
                            E + (size_t)(m0 + arow) * DIM + 0 + aq * 4, 16);
    __pipeline_memcpy_async(&Bs[0][brow * 16 + bn],
                            W + (size_t)(rowoff + 0 + brow) * HID + n0 + bn * 4, 16);
    __pipeline_commit();

    unsigned long long accp[4][2] = {};

    const int NC = DIM / 16;
    for (int c = 0; c < NC; c++) {
        if (c < NC - 1) {
            int bb = (c + 1) & 1;
            int k0 = (c + 1) * 16;
            __pipeline_memcpy_async(&As[bb][arow][aq * 4],
                                    E + (size_t)(m0 + arow) * DIM + k0 + aq * 4, 16);
            __pipeline_memcpy_async(&Bs[bb][brow * 16 + bn],
                                    W + (size_t)(rowoff + k0 + brow) * HID + n0 + bn * 4, 16);
            __pipeline_commit();
            __pipeline_wait_prior(1);
        } else {
            __pipeline_wait_prior(0);
        }
        __syncthreads();

        const float (*A)[20] = As[c & 1];
        const ulonglong2* B2 = (const ulonglong2*)Bs[c & 1];
        #pragma unroll
        for (int k = 0; k < 16; k++) {
            unsigned long long a0p, a1p, a2p, a3p;
            PACK2(a0p, A[ty * 4 + 0][k]);
            PACK2(a1p, A[ty * 4 + 1][k]);
            PACK2(a2p, A[ty * 4 + 2][k]);
            PACK2(a3p, A[ty * 4 + 3][k]);
            ulonglong2 b = B2[k * 16 + tx];
            FMA2(accp[0][0], a0p, b.x); FMA2(accp[0][1], a0p, b.y);
            FMA2(accp[1][0], a1p, b.x); FMA2(accp[1][1], a1p, b.y);
            FMA2(accp[2][0], a2p, b.x); FMA2(accp[2][1], a2p, b.y);
            FMA2(accp[3][0], a3p, b.x); FMA2(accp[3][1], a3p, b.y);
        }
        __syncthreads();
    }

    #pragma unroll
    for (int u = 0; u < 4; u++) {
        int gr = m0 + ty * 4 + u;
        int gc = n0 + tx * 4;
        float4 o;
        SPLIT2(o.x, o.y, accp[u][0]);
        SPLIT2(o.z, o.w, accp[u][1]);
        if (bias) { o.x += bias[gc]; o.y += bias[gc + 1]; o.z += bias[gc + 2]; o.w += bias[gc + 3]; }
        *(float4*)(g_G + (size_t)gr * (6 * HID) + colbase + gc) = o;
    }
}

// ---------------------------------------------------------------------------
__device__ __forceinline__ float warpsum(float v) {
    v += __shfl_xor_sync(0xffffffffu, v, 16);
    v += __shfl_xor_sync(0xffffffffu, v, 8);
    v += __shfl_xor_sync(0xffffffffu, v, 4);
    v += __shfl_xor_sync(0xffffffffu, v, 2);
    v += __shfl_xor_sync(0xffffffffu, v, 1);
    return v;
}

// libdevice erff: FMA-polynomial, no MUFU — keep everywhere (R5 lesson).
__device__ __forceinline__ float gelu_exact(float x) {
    return 0.5f * x * (1.0f + erff(x * 0.70710678118654752440f));
}

// ---------------------------------------------------------------------------
// prep: transpose c_j into g_GTc + per-entity (sum, sumsq) stats.
// ---------------------------------------------------------------------------
__global__ void __launch_bounds__(256) prep_kernel() {
    int b = blockIdx.x;
    int tid = threadIdx.x;
    if (b < 128) {
        __shared__ float t[32][33];
        int e0 = (b & 15) * 32;
        int d0 = (b >> 4) * 32;
        int tx = tid & 31, ty = tid >> 5;
        #pragma unroll
        for (int r = 0; r < 4; r++) {
            int row = ty + r * 8;
            t[row][tx] = g_G[(size_t)(e0 + row) * 1536 + 1024 + d0 + tx];
        }
        __syncthreads();
        #pragma unroll
        for (int r = 0; r < 4; r++) {
            int row = ty + r * 8;
            g_GTc[(size_t)(d0 + row) * NENT + e0 + tx] = t[tx][row];
        }
    } else {
        int warp = tid >> 5, lane = tid & 31;
        int e = (b - 128) * 8 + warp;
        const float* gr = g_G + (size_t)e * 1536;
        float s1 = 0.f, q1 = 0.f, s2 = 0.f, q2 = 0.f;
        #pragma unroll
        for (int q = 0; q < 8; q++) {
            float a = gr[256 + lane * 8 + q];
            float c = gr[1024 + lane * 8 + q];
            s1 += a; q1 = fmaf(a, a, q1);
            s2 += c; q2 = fmaf(c, c, q2);
        }
        s1 = warpsum(s1); q1 = warpsum(q1); s2 = warpsum(s2); q2 = warpsum(q2);
        if (lane == 0) {
            float4 o; o.x = s1; o.y = q1; o.z = s2; o.w = q2;
            *(float4*)(g_stats + e * 4) = o;
        }
    }
}

// ---------------------------------------------------------------------------
// dotc[i][j] = hi_c[i] . hj_c[j]
// ---------------------------------------------------------------------------
__global__ void __launch_bounds__(256) dotc_kernel() {
    __shared__ float As[64][17];
    __shared__ float Bs2[64][17];

    int m0 = blockIdx.y * 64;
    int n0 = blockIdx.x * 64;
    int tid = threadIdx.x;
    int tx = tid & 15, ty = tid >> 4;
    int lrow = tid >> 2, lkq = tid & 3;

    float acc[4][4] = {};

    for (int k0 = 0; k0 < HID; k0 += 16) {
        __syncthreads();
        {
            float4 a = *(const float4*)(g_G + (size_t)(m0 + lrow) * 1536 + 256 + k0 + lkq * 4);
            As[lrow][lkq * 4 + 0] = a.x; As[lrow][lkq * 4 + 1] = a.y;
            As[lrow][lkq * 4 + 2] = a.z; As[lrow][lkq * 4 + 3] = a.w;
            float4 c = *(const float4*)(g_G + (size_t)(n0 + lrow) * 1536 + 1024 + k0 + lkq * 4);
            Bs2[lrow][lkq * 4 + 0] = c.x; Bs2[lrow][lkq * 4 + 1] = c.y;
            Bs2[lrow][lkq * 4 + 2] = c.z; Bs2[lrow][lkq * 4 + 3] = c.w;
        }
        __syncthreads();
        #pragma unroll
        for (int k = 0; k < 16; k++) {
            float a0 = As[ty * 4 + 0][k], a1 = As[ty * 4 + 1][k];
            float a2 = As[ty * 4 + 2][k], a3 = As[ty * 4 + 3][k];
            float b0 = Bs2[tx * 4 + 0][k], b1 = Bs2[tx * 4 + 1][k];
            float b2 = Bs2[tx * 4 + 2][k], b3 = Bs2[tx * 4 + 3][k];
            acc[0][0] = fmaf(a0, b0, acc[0][0]); acc[0][1] = fmaf(a0, b1, acc[0][1]);
            acc[0][2] = fmaf(a0, b2, acc[0][2]); acc[0][3] = fmaf(a0, b3, acc[0][3]);
            acc[1][0] = fmaf(a1, b0, acc[1][0]); acc[1][1] = fmaf(a1, b1, acc[1][1]);
            acc[1][2] = fmaf(a1, b2, acc[1][2]); acc[1][3] = fmaf(a1, b3, acc[1][3]);
            acc[2][0] = fmaf(a2, b0, acc[2][0]); acc[2][1] = fmaf(a2, b1, acc[2][1]);
            acc[2][2] = fmaf(a2, b2, acc[2][2]); acc[2][3] = fmaf(a2, b3, acc[2][3]);
            acc[3][0] = fmaf(a3, b0, acc[3][0]); acc[3][1] = fmaf(a3, b1, acc[3][1]);
            acc[3][2] = fmaf(a3, b2, acc[3][2]); acc[3][3] = fmaf(a3, b3, acc[3][3]);
        }
    }
    #pragma unroll
    for (int u = 0; u < 4; u++) {
        float4 o; o.x = acc[u][0]; o.y = acc[u][1]; o.z = acc[u][2]; o.w = acc[u][3];
        *(float4*)(g_dotc + (size_t)(m0 + ty * 4 + u) * NENT + n0 + tx * 4) = o;
    }
}

// ---------------------------------------------------------------------------
// pair_c: cp.async double-buffered staging + FFMA2 weight-multiply (R14/R15).
// ---------------------------------------------------------------------------
#define PAIRC_SMEM ((2 * 16 * 256 + 256 * 16 + 2 * 256 + 256 + 16) * 4)

__global__ void __launch_bounds__(256) pairc_kernel(
    const float* __restrict__ cW2, const float* __restrict__ cb2,
    const float* __restrict__ c_g, const float* __restrict__ c_b,
    float* __restrict__ out)
{
    extern __shared__ float shc[];
    float*  sh_x    = shc;                             // [2][16][256]
    float*  sh_c2   = shc + 8192;                      // [256][16]
    float2* sh_gb   = (float2*)(shc + 8192 + 4096);    // [256]
    float*  sh_hic  = shc + 8192 + 4096 + 512;         // [256]
    float*  sh_cb2v = sh_hic + 256;                    // [16]

    int tid = threadIdx.x;
    int i = blockIdx.y;
    int j0 = blockIdx.x * 256;
    int j = j0 + tid;

    #pragma unroll
    for (int q = 0; q < 4; q++) {
        int f = q * 256 + tid;
        int dl = f >> 6, c4 = f & 63;
        __pipeline_memcpy_async(sh_x + dl * 256 + c4 * 4,
                                g_GTc + (size_t)dl * NENT + j0 + c4 * 4, 16);
    }
    __pipeline_commit();

    sh_hic[tid] = g_G[(size_t)i * 1536 + 256 + tid];
    sh_gb[tid] = make_float2(c_g[tid], c_b[tid]);
    for (int k = tid; k < 1024; k += 256)
        ((float4*)sh_c2)[k] = ((const float4*)cW2)[k];
    if (tid < 16) sh_cb2v[tid] = cb2[tid];

    const float inv256 = 1.0f / 256.0f;
    float4 stj = *(const float4*)(g_stats + j * 4);
    float S1 = g_stats[i * 4 + 0];
    float Q1 = g_stats[i * 4 + 1];
    float dot = g_dotc[(size_t)i * NENT + j];
    float m = (S1 + stj.z) * inv256;
    float var = fmaf(-m, m, (Q1 + 2.0f * dot + stj.w) * inv256);
    float rs = rsqrtf(var + 1e-5f);

    unsigned long long vp[8];
    #pragma unroll
    for (int t = 0; t < 8; t++) vp[t] = 0ull;

    __syncthreads();

    for (int c = 0; c < 16; c++) {
        if (c < 15) {
            int bb = (c + 1) & 1;
            #pragma unroll
            for (int q = 0; q < 4; q++) {
                int f = q * 256 + tid;
                int dl = f >> 6, c4 = f & 63;
                int d = (c + 1) * 16 + dl;
                __pipeline_memcpy_async(sh_x + bb * 4096 + dl * 256 + c4 * 4,
                                        g_GTc + (size_t)d * NENT + j0 + c4 * 4, 16);
            }
            __pipeline_commit();
            __pipeline_wait_prior(1);
        } else {
            __pipeline_wait_prior(0);
        }
        __syncthreads();

        const float* xb = sh_x + (c & 1) * 4096;
        #pragma unroll
        for (int dl = 0; dl < 16; dl++) {
            int d = c * 16 + dl;
            float x = xb[dl * 256 + tid] + sh_hic[d];
            float2 gb = sh_gb[d];
            float hn = fmaf((x - m) * rs, gb.x, gb.y);
            float ge = gelu_exact(hn);
            unsigned long long gep;
            PACK2(gep, ge);
            const ulonglong2* w2 = (const ulonglong2*)(sh_c2 + d * 16);
            ulonglong2 q0 = w2[0], q1 = w2[1], q2 = w2[2], q3 = w2[3];
            FMA2(vp[0], gep, q0.x); FMA2(vp[1], gep, q0.y);
            FMA2(vp[2], gep, q1.x); FMA2(vp[3], gep, q1.y);
            FMA2(vp[4], gep, q2.x); FMA2(vp[5], gep, q2.y);
            FMA2(vp[6], gep, q3.x); FMA2(vp[7], gep, q3.y);
        }
        __syncthreads();
    }

    float* orow = out + ((size_t)i * NENT + j) * 18 + 1;
    #pragma unroll
    for (int t = 0; t < 8; t++) {
        float lo, hi;
        SPLIT2(lo, hi, vp[t]);
        orow[2 * t + 0] = lo + sh_cb2v[2 * t + 0];
        orow[2 * t + 1] = hi + sh_cb2v[2 * t + 1];
    }
}

// ---------------------------------------------------------------------------
// pair_a: s + d heads, f32x2-packed (R15, bit-identical). selout zeroing
// lives in clear_kernel — one fewer scattered store per pair.
// ---------------------------------------------------------------------------
__global__ void __launch_bounds__(256, 4) paira_kernel(
    const float* __restrict__ sW2, const float* __restrict__ sb2,
    const float* __restrict__ s_g, const float* __restrict__ s_b,
    const float* __restrict__ dW2, const float* __restrict__ db2,
    const int* __restrict__ ebatch,
    float* __restrict__ out)
{
    extern __shared__ float sh[];
    float* sh_hj  = sh;                       // [2][TJ][256]  (s_j, d_j)
    float* sh_sg  = sh + 2 * TJ * 256;        // 256
    float* sh_sb  = sh_sg + 256;
    int*   sh_jb  = (int*)(sh_sb + 256);      // 16

    int i0 = blockIdx.y * TI, j0 = blockIdx.x * TJ;
    int tid = threadIdx.x, warp = tid >> 5, lane = tid & 31;

    for (int v = tid; v < 2 * TJ * 64; v += 256) {
        int h = v / (TJ * 64); int rem = v % (TJ * 64);
        int jj = rem / 64; int c4 = rem % 64;
        float4 val = *(const float4*)(g_G + (size_t)(j0 + jj) * 1536 + (3 + 2 * h) * 256 + c4 * 4);
        *(float4*)(sh_hj + ((h * TJ + jj) * 256) + c4 * 4) = val;
    }
    { int c = tid; sh_sg[c] = s_g[c]; sh_sb[c] = s_b[c]; }
    if (tid < 16) sh_jb[tid] = ebatch[j0 + tid];
    __syncthreads();

    int i = i0 + warp;
    int d0 = lane * 8;

    unsigned long long hisp[4], hidp[4];
    {
        const unsigned long long* gr64 = (const unsigned long long*)(g_G + (size_t)i * 1536);
        int h0 = lane * 4;
        #pragma unroll
        for (int h = 0; h < 4; h++) {
            hisp[h] = gr64[h0 + h];          // floats [d0, d0+8)
            hidp[h] = gr64[256 + h0 + h];    // floats [512+d0, 512+d0+8)
        }
    }
    float s2[8], d2v[8];
    #pragma unroll
    for (int q = 0; q < 8; q++) { s2[q] = sW2[d0 + q]; d2v[q] = dW2[d0 + q]; }

    float sbias2 = sb2[0], dbias2 = db2[0];
    int bi = ebatch[i];
    const float inv256 = 1.0f / 256.0f;
    const unsigned long long* sg64 = (const unsigned long long*)(sh_sg + d0);
    const unsigned long long* sb64 = (const unsigned long long*)(sh_sb + d0);

    for (int jj = 0; jj < TJ; jj++) {
        int j = j0 + jj;

        // -------- s head (bit-identical op sequence) --------
        const unsigned long long* hj64 =
            (const unsigned long long*)(sh_hj + (0 * TJ + jj) * 256 + d0);
        unsigned long long xp[4];
        float x[8];
        #pragma unroll
        for (int h = 0; h < 4; h++) {
            unsigned long long hjp = hj64[h];
            ADD2(xp[h], hisp[h], hjp);
            SPLIT2(x[2 * h], x[2 * h + 1], xp[h]);
        }
        float ps = 0.f;
        #pragma unroll
        for (int q = 0; q < 8; q++) ps += x[q];
        float m = warpsum(ps) * inv256;
        float nm = -m;
        unsigned long long nm2;
        PACK2(nm2, nm);
        unsigned long long ddp[4];
        float dd[8];
        #pragma unroll
        for (int h = 0; h < 4; h++) {
            ADD2(ddp[h], xp[h], nm2);
            SPLIT2(dd[2 * h], dd[2 * h + 1], ddp[h]);
        }
        float pv = 0.f;
        #pragma unroll
        for (int q = 0; q < 8; q++) pv = fmaf(dd[q], dd[q], pv);
        float rs = rsqrtf(warpsum(pv) * inv256 + 1e-5f);
        unsigned long long rs2;
        PACK2(rs2, rs);
        float acc = 0.f;
        #pragma unroll
        for (int h = 0; h < 4; h++) {
            unsigned long long t, hnp;
            MUL2(t, ddp[h], rs2);
            FMA2O(hnp, t, sg64[h], sb64[h]);
            float hn0, hn1;
            SPLIT2(hn0, hn1, hnp);
            acc = fmaf(gelu_exact(hn0), s2[2 * h + 0], acc);
            acc = fmaf(gelu_exact(hn1), s2[2 * h + 1], acc);
        }
        acc = warpsum(acc);
        float score = 1.0f / (1.0f + expf(-(acc + sbias2)));

        // -------- d head --------
        const unsigned long long* hjd64 =
            (const unsigned long long*)(sh_hj + (1 * TJ + jj) * 256 + d0);
        float acc2 = 0.f;
        #pragma unroll
        for (int h = 0; h < 4; h++) {
            unsigned long long xxp;
            ADD2(xxp, hidp[h], hjd64[h]);
            float xx0, xx1;
            SPLIT2(xx0, xx1, xxp);
            acc2 = fmaf(gelu_exact(xx0), d2v[2 * h + 0], acc2);
            acc2 = fmaf(gelu_exact(xx1), d2v[2 * h + 1], acc2);
        }
        acc2 = warpsum(acc2);
        float dir = 1.0f / (1.0f + expf(-(acc2 + dbias2)));

        if (lane == 0) {
            size_t pidx = (size_t)i * NENT + j;
            float* orow = out + pidx * 18;
            orow[0]  = score;
            orow[17] = dir;
            int cand = (bi == sh_jb[jj]) && (i != j) && (score >= 0.5f);
            if (cand) {
                int pos = atomicAdd(&g_ncand, 1);
                atomicAdd(&g_ncand_b[bi], 1);
                if (pos < PAD) {
                    unsigned bits = __float_as_uint(score);
                    unsigned long long key =
                        ((unsigned long long)(unsigned)bi << 42) |
                        ((unsigned long long)(bits - 0x3F000000u) << 18) |
                        (unsigned long long)((~(unsigned)pidx) & 0x3FFFFu);
                    g_ckeys[pos] = key;
                }
            }
        }
    }
}

// ---------------------------------------------------------------------------
// Greedy quota filter — batch-parallel: 4 warps, one per batch segment.
// ---------------------------------------------------------------------------
__global__ void __launch_bounds__(128) greedy_kernel(
    const unsigned long long* __restrict__ keys_s, float* __restrict__ selout)
{
    __shared__ int counts[NENT];
    __shared__ unsigned em[NENT];

    int tid = threadIdx.x;
    for (int e = tid; e < NENT; e += 128) { counts[e] = 0; em[e] = 0u; }
    __syncthreads();

    int warp = tid >> 5, lane = tid & 31;
    unsigned lt = (1u << lane) - 1u;

    int c3 = g_ncand_b[3], c2 = g_ncand_b[2], c1 = g_ncand_b[1], c0 = g_ncand_b[0];
    int b = 3 - warp;
    int start, len;
    if      (b == 3) { start = 0;            len = c3; }
    else if (b == 2) { start = c3;           len = c2; }
    else if (b == 1) { start = c3 + c2;      len = c1; }
    else             { start = c3 + c2 + c1; len = c0; }
    int end = start + len;
    if (end > PAD) end = PAD;

    unsigned long long knext = (start + lane < end) ? __ldg(keys_s + start + lane) : 0ull;

    for (int base = start; base < end; base += 32) {
        unsigned long long k = knext;
        int nb = base + 32;
        knext = (nb + lane < end) ? __ldg(keys_s + nb + lane) : 0ull;

        int active = (base + lane) < end;
        unsigned pidx = (~(unsigned)k) & 0x3FFFFu;
        int s = pidx >> 9, t = pidx & (NENT - 1);
        int cs = counts[s], ct = counts[t];
        int pre = active && (cs < 5) && (ct < 5);
        unsigned pm = __ballot_sync(0xffffffffu, pre);
        if (!pm) continue;

        if (pre) { atomicOr(&em[s], 1u << lane); atomicOr(&em[t], 1u << lane); }
        __syncwarp();
        unsigned Ms = 0u, Mt = 0u;
        if (pre) { Ms = em[s]; Mt = em[t]; }
        int ub_s = __popc(Ms & lt);
        int ub_t = __popc(Mt & lt);
        int sure = pre && (cs + ub_s < 5) && (ct + ub_t < 5);
        unsigned smask = __ballot_sync(0xffffffffu, sure);
        unsigned u = pm & ~smask;
        int accepted = sure;
        if (u) {
            int ok = 0;
            int es = __popc(Ms & smask & lt);
            int et = __popc(Mt & smask & lt);
            unsigned uu = u;
            while (uu) {
                int l = __ffs(uu) - 1;
                int okl_local = ((cs + es) < 5) && ((ct + et) < 5);
                int okl = __shfl_sync(0xffffffffu, okl_local, l);
                int sl  = __shfl_sync(0xffffffffu, s, l);
                int tl  = __shfl_sync(0xffffffffu, t, l);
                if (okl) {
                    es += (sl == s) + (tl == s);
                    et += (sl == t) + (tl == t);
                    if (lane == l) ok = 1;
                }
                uu &= uu - 1;
            }
            accepted |= ok;
        }
        if (accepted) {
            atomicAdd(&counts[s], 1);
            atomicAdd(&counts[t], 1);
            selout[pidx] = 1.0f;
        }
        __syncwarp();
        if (pre) { em[s] = 0u; em[t] = 0u; }
        __syncwarp();
    }
}

// ---------------------------------------------------------------------------
extern "C" void kernel_launch(void* const* d_in, const int* in_sizes, int n_in,
                              void* d_out, int out_size) {
    const float* E      = (const float*)d_in[0];
    const int*   ebatch = (const int*)d_in[1];
    const float* sW1 = (const float*)d_in[3];
    const float* sb1 = (const float*)d_in[4];
    const float* s_g = (const float*)d_in[5];
    const float* s_b = (const float*)d_in[6];
    const float* sW2 = (const float*)d_in[7];
    const float* sb2 = (const float*)d_in[8];
    const float* cW1 = (const float*)d_in[9];
    const float* cb1 = (const float*)d_in[10];
    const float* c_g = (const float*)d_in[11];
    const float* c_b = (const float*)d_in[12];
    const float* cW2 = (const float*)d_in[13];
    const float* cb2 = (const float*)d_in[14];
    const float* dW1 = (const float*)d_in[15];
    const float* db1 = (const float*)d_in[16];
    const float* dW2 = (const float*)d_in[17];
    const float* db2 = (const float*)d_in[18];

    float* out = (float*)d_out;
    float* selout = out + ((size_t)out_size - NN);

    // Stream/events created ONCE on the first call (precedes the harness's
    // pre-capture memory baseline), reused thereafter — R12 leak fix.
    static cudaStream_t s2 = nullptr;
    static cudaEvent_t evF = nullptr, evJ = nullptr;
    if (s2 == nullptr) {
        cudaStreamCreate(&s2);
        cudaEventCreateWithFlags(&evF, cudaEventDisableTiming);
        cudaEventCreateWithFlags(&evJ, cudaEventDisableTiming);
        cudaFuncSetAttribute(pairc_kernel, cudaFuncAttributeMaxDynamicSharedMemorySize, PAIRC_SMEM);
        cudaFuncSetAttribute(paira_kernel, cudaFuncAttributeMaxDynamicSharedMemorySize,
                             (2 * TJ * 256 + 2 * 256) * 4 + 16 * 4);
    }
    int shbytes = (2 * TJ * 256 + 2 * 256) * 4 + 16 * 4;

    // R11/R15 topology: unified gemm6 first, then fork the c-chain.
    clear_kernel<<<256, 256>>>(selout);
    gemm6_kernel<<<dim3(HID / 64, NENT / 64, 6), 256>>>(E, sW1, cW1, dW1, sb1, cb1, db1);

    cudaEventRecord(evF, 0);
    cudaStreamWaitEvent(s2, evF, 0);

    // stream 0: paira -> sort -> greedy
    paira_kernel<<<dim3(NENT / TJ, NENT / TI), 256, shbytes>>>(
        sW2, sb2, s_g, s_b, dW2, db2, ebatch, out);

    // stream s2: prep -> dotc -> pairc
    prep_kernel<<<192, 256, 0, s2>>>();
    dotc_kernel<<<dim3(NENT / 64, NENT / 64), 256, 0, s2>>>();
    pairc_kernel<<<dim3(NENT / 256, NENT), 256, PAIRC_SMEM, s2>>>(cW2, cb2, c_g, c_b, out);
    cudaEventRecord(evJ, s2);

    void *pck, *pcks, *ptmp;
    cudaGetSymbolAddress(&pck,  g_ckeys);
    cudaGetSymbolAddress(&pcks, g_ckeys_s);
    cudaGetSymbolAddress(&ptmp, g_sort_tmp);
    size_t tb = 0;
    cub::DeviceRadixSort::SortKeysDescending(nullptr, tb,
        (const unsigned long long*)pck, (unsigned long long*)pcks, PAD, 0, 44, 0);
    if (tb > (size_t)(16u << 20)) tb = (size_t)(16u << 20);
    cub::DeviceRadixSort::SortKeysDescending(ptmp, tb,
        (const unsigned long long*)pck, (unsigned long long*)pcks, PAD, 0, 44, 0);

    greedy_kernel<<<1, 128>>>((const unsigned long long*)pcks, selout);

    // join pairc chain back into stream 0 before capture ends
    cudaStreamWaitEvent(0, evJ, 0);
}